// round 2
// baseline (speedup 1.0000x reference)
#include <cuda_runtime.h>
#include <cuda_bf16.h>

// Problem dims (fixed by the dataset)
#define Hn 256
#define Bn 128
#define Tn 1000
#define Fn 20
#define On 200
#define TPB 512          // 16 warps; 8 gather groups x 64 float4 lanes

// Scratch: preprocessed weight matrices (fp32, gather-friendly layouts).
// ~968 KB total; static __device__ globals (no runtime allocation).
__device__ __align__(16) float g_V1z[Hn * Hn];   // Vrec1 with zero diag, [j][h]
__device__ __align__(16) float g_W2t[Hn * Hn];   // W2 transposed: W2t[j][h] = W2[h][j]
__device__ __align__(16) float g_V2z[Hn * Hn];   // Vrec2 with zero diag, [j][h]
__device__ __align__(16) float g_WoT[Hn * On];   // Wout transposed: WoT[j][o] = Wout[o][j]

__global__ void prep_kernel(const float* __restrict__ Vrec1,
                            const float* __restrict__ W2,
                            const float* __restrict__ Vrec2,
                            const float* __restrict__ Wout) {
    int idx = blockIdx.x * 256 + threadIdx.x;   // grid 256x256 -> 65536
    int j = idx >> 8, h = idx & 255;
    g_V1z[idx] = (j == h) ? 0.0f : Vrec1[idx];
    g_V2z[idx] = (j == h) ? 0.0f : Vrec2[idx];
    g_W2t[idx] = W2[h * Hn + j];
    if (idx < Hn * On) {
        int jj = idx / On;
        int o  = idx - jj * On;
        g_WoT[idx] = Wout[o * Hn + jj];
    }
}

// One CTA per batch element. 512 threads:
//   - thread tid (<256) owns neuron tid of layer1 & layer2 (output neuron tid if <200)
//   - gathers: g = tid>>6 (list chunk 0..7), q = tid&63 (float4 column lane)
__global__ __launch_bounds__(TPB) void snn_kernel(
    const float* __restrict__ x,
    const float* __restrict__ W1, const float* __restrict__ b1, const float* __restrict__ beta1,
    const float* __restrict__ b2, const float* __restrict__ beta2,
    const float* __restrict__ alpha_out, const float* __restrict__ beta_out,
    float* __restrict__ out)
{
    const int tid  = threadIdx.x;
    const int b    = blockIdx.x;
    const int lane = tid & 31, warp = tid >> 5;
    const int g    = tid >> 6;        // 0..7
    const int q    = tid & 63;        // 0..63

    __shared__ float4 pacc[TPB];                    // partials: 8 groups x 64 quads
    __shared__ unsigned short l1[2][Hn], l2[2][Hn]; // double-buffered spike index lists
    __shared__ unsigned sbal[8];
    __shared__ float redm[8], reds[8];

    float* paccf = (float*)pacc;

    // Per-neuron parameters (masked index for tid>=256 to stay in-bounds)
    const int pid = tid & 255;
    float w1r[Fn];
#pragma unroll
    for (int i = 0; i < Fn; i++) w1r[i] = W1[pid * Fn + i];
    const float b1r = b1[pid], be1 = beta1[pid];
    const float b2r = b2[pid], be2 = beta2[pid];
    float aor = 0.f, bor = 0.f;
    if (tid < On) { aor = alpha_out[tid]; bor = beta_out[tid]; }

    // States
    float syn1 = 0.f, mem1 = 0.f, sp1 = 0.f;
    float syn2 = 0.f, mem2 = 0.f, sp2 = 0.f;
    float syno = 0.f, memo = 0.f, spo = 0.f, acco = 0.f;

    const float4* V1q = ((const float4*)g_V1z) + q;
    const float4* W2q = ((const float4*)g_W2t) + q;
    const float4* V2q = ((const float4*)g_V2z) + q;
    const float4* Woq = ((const float4*)g_WoT) + q;   // only valid for q < 50

    const float4* xbv = (const float4*)(x + (size_t)b * (Tn * Fn));  // 80B/step, 16B-aligned

    // Prefetch x[0] into registers (5 float4 = 20 floats)
    float4 xr[5];
    if (tid < Hn) {
#pragma unroll
        for (int i = 0; i < 5; i++) xr[i] = __ldg(xbv + i);
    }

    int c1p = 0, c2p = 0, p = 0;   // prev-step list counts + buffer parity
    __syncthreads();

    for (int t = 0; t < Tn; t++) {
        const int n = p ^ 1;

        // input drive from prefetched registers; then prefetch next step's x
        float wx = b1r;
        if (tid < Hn) {
            const float* xf = (const float*)xr;
#pragma unroll
            for (int i = 0; i < Fn; i++) wx += w1r[i] * xf[i];
            if (t + 1 < Tn) {
#pragma unroll
                for (int i = 0; i < 5; i++) xr[i] = __ldg(xbv + (t + 1) * 5 + i);
            }
        }

        // ============ PHASE 1: layer-1 recurrent drive ============
        float4 a = make_float4(0.f, 0.f, 0.f, 0.f);
        {
            const unsigned short* L = l1[p];
#pragma unroll 4
            for (int k = g; k < c1p; k += 8) {
                int j = L[k];
                float4 v = __ldg(V1q + (j << 6));
                a.x += v.x; a.y += v.y; a.z += v.z; a.w += v.w;
            }
        }
        pacc[tid] = a;
        __syncthreads();
        unsigned bal = 0u;
        if (tid < Hn) {
            float r = 0.f;
#pragma unroll
            for (int gg = 0; gg < 8; gg++) r += paccf[gg * 256 + tid];
            syn1 = 0.95f * syn1 + (wx + r);
            mem1 = be1 * mem1 + syn1 - sp1;        // detached reset uses PREVIOUS spike
            sp1  = (mem1 > 1.0f) ? 1.0f : 0.0f;    // spike(mem - THR), THR = 1
            bal = __ballot_sync(0xffffffffu, sp1 > 0.5f);
            if (lane == 0) sbal[warp] = bal;
        }
        __syncthreads();
        int c1c;
        {
            int pre = 0, tot = 0;
#pragma unroll
            for (int w = 0; w < 8; w++) {
                int c = __popc(sbal[w]);
                if (w < warp) pre += c;
                tot += c;
            }
            if (sp1 > 0.5f)
                l1[n][pre + __popc(bal & ((1u << lane) - 1u))] = (unsigned short)tid;
            c1c = tot;
        }
        __syncthreads();

        // ============ PHASE 2: layer-2 drive (feedforward + recurrent) ============
        a = make_float4(0.f, 0.f, 0.f, 0.f);
        {
            const unsigned short* L = l1[n];       // current-step layer-1 spikes
#pragma unroll 4
            for (int k = g; k < c1c; k += 8) {
                int j = L[k];
                float4 v = __ldg(W2q + (j << 6));
                a.x += v.x; a.y += v.y; a.z += v.z; a.w += v.w;
            }
        }
        {
            const unsigned short* L = l2[p];       // previous-step layer-2 spikes
#pragma unroll 4
            for (int k = g; k < c2p; k += 8) {
                int j = L[k];
                float4 v = __ldg(V2q + (j << 6));
                a.x += v.x; a.y += v.y; a.z += v.z; a.w += v.w;
            }
        }
        pacc[tid] = a;
        __syncthreads();
        unsigned bal2 = 0u;
        if (tid < Hn) {
            float r = 0.f;
#pragma unroll
            for (int gg = 0; gg < 8; gg++) r += paccf[gg * 256 + tid];
            syn2 = 0.95f * syn2 + (b2r + r);
            mem2 = be2 * mem2 + syn2 - sp2;
            sp2  = (mem2 > 1.0f) ? 1.0f : 0.0f;
            bal2 = __ballot_sync(0xffffffffu, sp2 > 0.5f);
            if (lane == 0) sbal[warp] = bal2;
        }
        __syncthreads();
        int c2c;
        {
            int pre = 0, tot = 0;
#pragma unroll
            for (int w = 0; w < 8; w++) {
                int c = __popc(sbal[w]);
                if (w < warp) pre += c;
                tot += c;
            }
            if (sp2 > 0.5f)
                l2[n][pre + __popc(bal2 & ((1u << lane) - 1u))] = (unsigned short)tid;
            c2c = tot;
        }
        __syncthreads();

        // ============ PHASE 3: readout + softmax accumulation ============
        a = make_float4(0.f, 0.f, 0.f, 0.f);
        if (q < 50) {                               // 200 outputs = 50 float4 lanes
            const unsigned short* L = l2[n];
#pragma unroll 4
            for (int k = g; k < c2c; k += 8) {
                int j = L[k];
                float4 v = __ldg(Woq + j * 50);
                a.x += v.x; a.y += v.y; a.z += v.z; a.w += v.w;
            }
        }
        pacc[tid] = a;
        __syncthreads();
        float mval = -3.4e38f;
        float e = 0.f;
        if (tid < On) {
            float ot = 0.f;
#pragma unroll
            for (int gg = 0; gg < 8; gg++) ot += paccf[gg * 256 + tid];
            syno = aor * syno + ot;
            memo = bor * memo + syno - spo;
            spo  = (memo > 1.0f) ? 1.0f : 0.0f;
            mval = memo;
        }
#pragma unroll
        for (int off = 16; off; off >>= 1)
            mval = fmaxf(mval, __shfl_xor_sync(0xffffffffu, mval, off));
        if (lane == 0 && warp < 8) redm[warp] = mval;
        __syncthreads();
        float m = redm[0];
#pragma unroll
        for (int w = 1; w < 7; w++) m = fmaxf(m, redm[w]);  // outputs live in warps 0..6
        if (tid < On) e = __expf(memo - m);
        float sv = e;
#pragma unroll
        for (int off = 16; off; off >>= 1)
            sv += __shfl_xor_sync(0xffffffffu, sv, off);
        if (lane == 0 && warp < 8) reds[warp] = sv;
        __syncthreads();
        float s = reds[0];
#pragma unroll
        for (int w = 1; w < 7; w++) s += reds[w];
        if (tid < On && t > 10) acco += e / s;      // step > WARMUP (=10)

        c1p = c1c; c2p = c2c; p = n;
    }

    if (tid < On) out[b * On + tid] = acco;
}

extern "C" void kernel_launch(void* const* d_in, const int* in_sizes, int n_in,
                              void* d_out, int out_size) {
    const float* x         = (const float*)d_in[0];
    const float* W1        = (const float*)d_in[1];
    const float* b1        = (const float*)d_in[2];
    const float* Vrec1     = (const float*)d_in[3];
    const float* beta1     = (const float*)d_in[4];
    const float* W2        = (const float*)d_in[5];
    const float* b2        = (const float*)d_in[6];
    const float* Vrec2     = (const float*)d_in[7];
    const float* beta2     = (const float*)d_in[8];
    const float* Wout      = (const float*)d_in[9];
    const float* alpha_out = (const float*)d_in[10];
    const float* beta_out  = (const float*)d_in[11];
    float* out = (float*)d_out;

    prep_kernel<<<256, 256>>>(Vrec1, W2, Vrec2, Wout);
    snn_kernel<<<Bn, TPB>>>(x, W1, b1, beta1, b2, beta2, alpha_out, beta_out, out);
}